// round 2
// baseline (speedup 1.0000x reference)
#include <cuda_runtime.h>

// Collapsed SimpleAttention: out[b,k] = (mean_s x[b,s,:]) @ Wv[:,k] + bv[k]
// (softmax over the query axis makes Q/K/att cancel exactly under mean-pool).
//
// k1 : balanced column-sum of x. grid (148, 8) = exactly 8 blocks/SM, one wave.
// k2a: reduce 148 partials -> xbar[b][d].
// k2b: xbar @ Wv + bv -> d_out (fused epilogue, no k3).

#define BB   8
#define SS   2048
#define DD   1024
#define DKK  512
#define NBLK 148          // k1 blocks per batch == SM count

__device__ float g_partial[BB * NBLK * DD];   // [b][j][d]  ~4.85 MB (L2-resident)
__device__ float g_xbar[BB * DD];             // [b][d]     32 KB

// ---------------------------------------------------------------------------
// k1: each block sums a ~14-row strip of x[b] into g_partial[b][j][:].
// 256 threads, thread t owns float4 at d = 4t. 4 loads in flight, 2 accums.
// launch_bounds(256,8): force <=32 regs so 8 blocks/SM co-reside (100% occ,
// single perfectly balanced wave of 1184 blocks on 148 SMs).
// ---------------------------------------------------------------------------
__global__ void __launch_bounds__(256, 8) k1_colsum(const float* __restrict__ x) {
    const int j = blockIdx.x;
    const int b = blockIdx.y;
    const int d = threadIdx.x * 4;

    const int r0 = (j * SS) / NBLK;
    const int r1 = ((j + 1) * SS) / NBLK;
    const int n  = r1 - r0;

    const float4* xp = reinterpret_cast<const float4*>(
        x + ((size_t)(b * SS + r0)) * DD + d);

    float4 a0 = make_float4(0.f, 0.f, 0.f, 0.f);
    float4 a1 = make_float4(0.f, 0.f, 0.f, 0.f);

    int s = 0;
    for (; s + 4 <= n; s += 4) {
        float4 v0 = xp[(size_t)(s + 0) * (DD / 4)];
        float4 v1 = xp[(size_t)(s + 1) * (DD / 4)];
        float4 v2 = xp[(size_t)(s + 2) * (DD / 4)];
        float4 v3 = xp[(size_t)(s + 3) * (DD / 4)];
        a0.x += v0.x; a0.y += v0.y; a0.z += v0.z; a0.w += v0.w;
        a1.x += v1.x; a1.y += v1.y; a1.z += v1.z; a1.w += v1.w;
        a0.x += v2.x; a0.y += v2.y; a0.z += v2.z; a0.w += v2.w;
        a1.x += v3.x; a1.y += v3.y; a1.z += v3.z; a1.w += v3.w;
    }
    for (; s < n; s++) {
        float4 v = xp[(size_t)s * (DD / 4)];
        a0.x += v.x; a0.y += v.y; a0.z += v.z; a0.w += v.w;
    }
    a0.x += a1.x; a0.y += a1.y; a0.z += a1.z; a0.w += a1.w;

    *reinterpret_cast<float4*>(g_partial + ((size_t)(b * NBLK + j)) * DD + d) = a0;
}

// ---------------------------------------------------------------------------
// k2a: xbar[b][d] = (1/SS) * sum_j g_partial[b][j][d].
// grid (4, 8), 256 thr: thread owns one d. Warp reads are 128B coalesced.
// ---------------------------------------------------------------------------
__global__ void __launch_bounds__(256) k2a_reduce() {
    const int b = blockIdx.y;
    const int d = blockIdx.x * 256 + threadIdx.x;
    const float* p = g_partial + (size_t)b * NBLK * DD + d;
    float s = 0.f;
#pragma unroll 4
    for (int j = 0; j < NBLK; j++)
        s += p[(size_t)j * DD];
    g_xbar[b * DD + d] = s * (1.0f / (float)SS);
}

// ---------------------------------------------------------------------------
// k2b: out[b][kbase+k] = sum_d xbar[b][d] * Wv[d][kbase+k] + bv[kbase+k].
// grid (4 ktiles of 128, 8 b), 256 thr.
// thread: lane = t&31 owns k = kbase + 4*lane (float4 Wv loads, warp = 512B
// contiguous); ds = t>>5 owns a 128-wide d slice. smem-reduce 8 d-slices.
// ---------------------------------------------------------------------------
__global__ void __launch_bounds__(256) k2b_gemm(const float* __restrict__ Wv,
                                                const float* __restrict__ bv,
                                                float* __restrict__ out) {
    __shared__ float  xb[DD];
    __shared__ float4 red[8][32];

    const int b     = blockIdx.y;
    const int kbase = blockIdx.x * 128;
    const int t     = threadIdx.x;
    const int lane  = t & 31;
    const int ds    = t >> 5;

    // load xbar[b][:] into smem (float4, coalesced)
    reinterpret_cast<float4*>(xb)[t] =
        reinterpret_cast<const float4*>(g_xbar + b * DD)[t];
    __syncthreads();

    const float* wbase = Wv + kbase + lane * 4;
    float4 acc = make_float4(0.f, 0.f, 0.f, 0.f);
    const int d0 = ds * 128;
#pragma unroll 4
    for (int d = d0; d < d0 + 128; d++) {
        const float4 w = *reinterpret_cast<const float4*>(wbase + (size_t)d * DKK);
        const float  xv = xb[d];
        acc.x += xv * w.x; acc.y += xv * w.y;
        acc.z += xv * w.z; acc.w += xv * w.w;
    }
    red[ds][lane] = acc;
    __syncthreads();

    if (t < 32) {
        float4 s = red[0][t];
#pragma unroll
        for (int i = 1; i < 8; i++) {
            s.x += red[i][t].x; s.y += red[i][t].y;
            s.z += red[i][t].z; s.w += red[i][t].w;
        }
        const float4 bb = *reinterpret_cast<const float4*>(bv + kbase + t * 4);
        s.x += bb.x; s.y += bb.y; s.z += bb.z; s.w += bb.w;
        *reinterpret_cast<float4*>(out + (size_t)b * DKK + kbase + t * 4) = s;
    }
}

// ---------------------------------------------------------------------------
// Inputs (metadata order): x, Wq, bq, Wk, bk, Wv, bv
// ---------------------------------------------------------------------------
extern "C" void kernel_launch(void* const* d_in, const int* in_sizes, int n_in,
                              void* d_out, int out_size) {
    const float* x  = (const float*)d_in[0];
    const float* Wv = (const float*)d_in[5];
    const float* bv = (const float*)d_in[6];
    float* out = (float*)d_out;

    k1_colsum<<<dim3(NBLK, BB), 256>>>(x);
    k2a_reduce<<<dim3(4, BB), 256>>>();
    k2b_gemm<<<dim3(4, BB), 256>>>(Wv, bv, out);
}

// round 3
// speedup vs baseline: 1.2672x; 1.2672x over previous
#include <cuda_runtime.h>

// Collapsed SimpleAttention: out[b,k] = (mean_s x[b,s,:]) @ Wv[:,k] + bv[k]
// (softmax over the query axis => sum_q att[b,q,s] = 1 => Q/K/att cancel
//  exactly under the mean-pool).
//
// k1: column-sum of x. R0's best-measured shape (512 blocks, contiguous
//     32-row strips, compile-time trip count) with MLP raised to 8
//     independent float4 loads in flight. No register cap.
// k2: fused reduce + GEMM + bias -> d_out. 32 blocks.

#define BB     8
#define SS     2048
#define DD     1024
#define DKK    512
#define NCHUNK 64
#define SCHUNK (SS / NCHUNK)   // 32 rows per block, compile-time

__device__ float g_partial[BB * NCHUNK * DD];   // [b][chunk][d]  2 MB

// ---------------------------------------------------------------------------
// k1: grid (NCHUNK, BB) = 512 blocks, 256 threads. Thread t owns the float4
// at column d = 4t. Each block reads a contiguous 128 KB strip of x.
// 8 independent loads in flight per thread (manual unroll, 4 accumulators).
// ---------------------------------------------------------------------------
__global__ void __launch_bounds__(256) k1_colsum(const float* __restrict__ x) {
    const int c = blockIdx.x;
    const int b = blockIdx.y;
    const int d = threadIdx.x * 4;

    const float4* xp = reinterpret_cast<const float4*>(
        x + ((size_t)(b * SS + c * SCHUNK)) * DD + d);
    const size_t rs = DD / 4;   // row stride in float4

    float4 a0 = make_float4(0.f, 0.f, 0.f, 0.f);
    float4 a1 = make_float4(0.f, 0.f, 0.f, 0.f);
    float4 a2 = make_float4(0.f, 0.f, 0.f, 0.f);
    float4 a3 = make_float4(0.f, 0.f, 0.f, 0.f);

#pragma unroll
    for (int s = 0; s < SCHUNK; s += 8) {
        const float4 v0 = xp[(s + 0) * rs];
        const float4 v1 = xp[(s + 1) * rs];
        const float4 v2 = xp[(s + 2) * rs];
        const float4 v3 = xp[(s + 3) * rs];
        const float4 v4 = xp[(s + 4) * rs];
        const float4 v5 = xp[(s + 5) * rs];
        const float4 v6 = xp[(s + 6) * rs];
        const float4 v7 = xp[(s + 7) * rs];
        a0.x += v0.x; a0.y += v0.y; a0.z += v0.z; a0.w += v0.w;
        a1.x += v1.x; a1.y += v1.y; a1.z += v1.z; a1.w += v1.w;
        a2.x += v2.x; a2.y += v2.y; a2.z += v2.z; a2.w += v2.w;
        a3.x += v3.x; a3.y += v3.y; a3.z += v3.z; a3.w += v3.w;
        a0.x += v4.x; a0.y += v4.y; a0.z += v4.z; a0.w += v4.w;
        a1.x += v5.x; a1.y += v5.y; a1.z += v5.z; a1.w += v5.w;
        a2.x += v6.x; a2.y += v6.y; a2.z += v6.z; a2.w += v6.w;
        a3.x += v7.x; a3.y += v7.y; a3.z += v7.z; a3.w += v7.w;
    }
    a0.x += a1.x; a0.y += a1.y; a0.z += a1.z; a0.w += a1.w;
    a2.x += a3.x; a2.y += a3.y; a2.z += a3.z; a2.w += a3.w;
    a0.x += a2.x; a0.y += a2.y; a0.z += a2.z; a0.w += a2.w;

    *reinterpret_cast<float4*>(g_partial + ((size_t)(b * NCHUNK + c)) * DD + d) = a0;
}

// ---------------------------------------------------------------------------
// k2: fused reduce + GEMM + bias. grid (4 ktiles x 8 b), 256 threads.
// Phase 1: each block reduces all 64 partials -> xbar[1024] in smem
//          (thread t owns float4 at d = 4t; fully coalesced, L2-resident).
// Phase 2: lane owns k = kbase + 4*lane (float4 Wv loads, 512B/warp
//          contiguous); warp ds owns a 128-wide d slice; smem-reduce.
// ---------------------------------------------------------------------------
__global__ void __launch_bounds__(256) k2_gemm(const float* __restrict__ Wv,
                                               const float* __restrict__ bv,
                                               float* __restrict__ out) {
    __shared__ float  xb[DD];
    __shared__ float4 red[8][32];

    const int b     = blockIdx.y;
    const int kbase = blockIdx.x * 128;
    const int t     = threadIdx.x;
    const int lane  = t & 31;
    const int ds    = t >> 5;

    // Phase 1: reduce partials -> xbar (each thread one float4 column group)
    {
        const float4* p = reinterpret_cast<const float4*>(
            g_partial + (size_t)b * NCHUNK * DD) + t;
        float4 s = make_float4(0.f, 0.f, 0.f, 0.f);
#pragma unroll 8
        for (int j = 0; j < NCHUNK; j++) {
            const float4 v = p[(size_t)j * (DD / 4)];
            s.x += v.x; s.y += v.y; s.z += v.z; s.w += v.w;
        }
        const float inv = 1.0f / (float)SS;
        s.x *= inv; s.y *= inv; s.z *= inv; s.w *= inv;
        reinterpret_cast<float4*>(xb)[t] = s;
    }
    __syncthreads();

    // Phase 2: GEMM slice
    const float* wbase = Wv + kbase + lane * 4;
    float4 acc = make_float4(0.f, 0.f, 0.f, 0.f);
    const int d0 = ds * 128;
#pragma unroll 4
    for (int d = d0; d < d0 + 128; d++) {
        const float4 w  = *reinterpret_cast<const float4*>(wbase + (size_t)d * DKK);
        const float  xv = xb[d];
        acc.x += xv * w.x; acc.y += xv * w.y;
        acc.z += xv * w.z; acc.w += xv * w.w;
    }
    red[ds][lane] = acc;
    __syncthreads();

    if (t < 32) {
        float4 s = red[0][t];
#pragma unroll
        for (int i = 1; i < 8; i++) {
            s.x += red[i][t].x; s.y += red[i][t].y;
            s.z += red[i][t].z; s.w += red[i][t].w;
        }
        const float4 bb = *reinterpret_cast<const float4*>(bv + kbase + t * 4);
        s.x += bb.x; s.y += bb.y; s.z += bb.z; s.w += bb.w;
        *reinterpret_cast<float4*>(out + (size_t)b * DKK + kbase + t * 4) = s;
    }
}

// ---------------------------------------------------------------------------
// Inputs (metadata order): x, Wq, bq, Wk, bk, Wv, bv
// ---------------------------------------------------------------------------
extern "C" void kernel_launch(void* const* d_in, const int* in_sizes, int n_in,
                              void* d_out, int out_size) {
    const float* x  = (const float*)d_in[0];
    const float* Wv = (const float*)d_in[5];
    const float* bv = (const float*)d_in[6];
    float* out = (float*)d_out;

    k1_colsum<<<dim3(NCHUNK, BB), 256>>>(x);
    k2_gemm<<<dim3(4, BB), 256>>>(Wv, bv, out);
}